// round 9
// baseline (speedup 1.0000x reference)
#include <cuda_runtime.h>
#include <math.h>

#define NF   24
#define FS   8
#define DY   32
#define DX   32
#define SEQL 300
#define TOTAL (NF*FS*DY*DX*SEQL)   // 58,982,400 floats
#define N4    (TOTAL/4)            // 14,745,600 float4
#define ROW4  75

#define B1    450                  // grid size; 450*256 threads, ALL co-resident
#define THR   256
#define T1    (B1*THR)             // 115200 = 75*1536 -> t%75 loop-invariant
#define SLOTS (N4/T1)              // 128 float4 per thread

#define FS_STRIDE (DY*DX*SEQL)     // 307200 floats between fs slices
#define B_POS     (NF*16*10)       // 3840 bbox spatial positions

__device__ float    g_partial[B1];
__device__ unsigned g_count;           // 0 after every run (zero-init)
__device__ volatile unsigned g_sense;  // flips each run (sense-reversing barrier)

// Hand-evaluated Python bbox math: left = int(32*l), w = int(32*round(l+0.3,4)) - left
__constant__ int c_left[NF] = {
    1, 2, 2, 3, 4, 5, 5, 6, 7, 7, 8, 9,
    9, 10, 11, 12, 12, 13, 14, 14, 15, 16, 16, 17
};
__constant__ int c_w[NF] = {
    10, 9, 10, 10, 9, 9, 10, 10, 9, 10, 10, 9,
    10, 10, 9, 9, 10, 10, 9, 10, 10, 9, 10, 10
};
__constant__ int c_edge_tok[6] = {2, 3, 9, 10, 11, 108};

// selected token: s==2 || s==3 || 9<=s<=108
__device__ __forceinline__ bool sel_tok(int s) {
    return ((unsigned)(s - 9) < 100u) || ((s & ~1) == 2);
}

// normalized gaussian weight for (yrow, xoff) given bbox width w (9 or 10)
__device__ __forceinline__ float gauss_w(int yrow, int xoff, int w) {
    const float dx = (float)yrow * (16.0f / 15.0f) - 8.0f;
    float ax = ((8.0f / 15.0f) * (8.0f / 15.0f) - dx * dx) * (9.0f / 512.0f);
    float dy, dymin2, inv2sy2;
    if (w == 10) {
        dy = (float)xoff * (10.0f / 9.0f) - 5.0f;
        dymin2 = (5.0f / 9.0f) * (5.0f / 9.0f);
        inv2sy2 = 9.0f / 200.0f;
    } else {
        dy = (float)xoff * (9.0f / 8.0f) - 4.0f;
        dymin2 = 0.25f;
        inv2sy2 = 1.0f / 18.0f;
    }
    return __expf(ax + (dymin2 - dy * dy) * inv2sy2);
}

__global__ void __launch_bounds__(THR, 4)
fused_kernel(const float4* __restrict__ in4, float4* __restrict__ out4,
             const float* __restrict__ in, float* __restrict__ out) {
    const int tid  = threadIdx.x;
    const int bid  = blockIdx.x;
    const int lane = tid & 31;
    const int wid  = tid >> 5;
    const unsigned cur_sense = g_sense;   // read before anyone can flip it

    __shared__ float sm[8];
    __shared__ float s_gmax;

    // ================= phase 1: weaken + max (472 MB stream) =================
    const int t  = bid * THR + tid;
    const int s0 = (t % ROW4) * 4;        // invariant across all 128 slots
    float4 m;
    m.x = sel_tok(s0    ) ? 0.918f : 1.0f;
    m.y = sel_tok(s0 + 1) ? 0.918f : 1.0f;
    m.z = sel_tok(s0 + 2) ? 0.918f : 1.0f;
    m.w = sel_tok(s0 + 3) ? 0.918f : 1.0f;

    float mx = 0.f;
    #pragma unroll 4
    for (int k = 0; k < SLOTS; k++) {
        const int i = t + k * T1;
        float4 x = __ldcs(in4 + i);
        mx = fmaxf(mx, fmaxf(fmaxf(x.x, x.y), fmaxf(x.z, x.w)));
        __stcs(out4 + i, make_float4(x.x * m.x, x.y * m.y, x.z * m.z, x.w * m.w));
    }

    // block max -> g_partial[bid]
    #pragma unroll
    for (int off = 16; off; off >>= 1)
        mx = fmaxf(mx, __shfl_xor_sync(0xffffffffu, mx, off));
    if (lane == 0) sm[wid] = mx;
    __syncthreads();
    if (tid < 8) {
        mx = sm[tid];
        #pragma unroll
        for (int off = 4; off; off >>= 1)
            mx = fmaxf(mx, __shfl_xor_sync(0xffu, mx, off));
        if (tid == 0) g_partial[bid] = mx;
    }

    // ========== phase 2 prelude: decode + gaussian + PRELOAD (no g_max) ======
    // one warp per bbox position gw in [0,3600); positions 3600..3839 later.
    const int gw = bid * 8 + wid;
    int pos = gw;
    const int xoff = pos % 10;  pos /= 10;
    const int yrow = pos & 15;
    const int f    = pos >> 4;
    const int w    = c_w[f];
    const bool active = (xoff < w);

    float  gauss = 0.f;
    long   base  = 0;
    float4 v[FS];
    float  vs[FS];
    const int tok4 = 12 + 4 * lane;                                   // lane<24
    const int toke = (lane >= 24 && lane < 30) ? c_edge_tok[lane - 24] : 0;

    if (active) {
        gauss = gauss_w(yrow, xoff, w);
        base  = (long)(f * FS * DY + 8 + yrow) * DX * SEQL
              + (long)(c_left[f] + xoff) * SEQL;
        if (lane < 24) {
            #pragma unroll
            for (int r = 0; r < FS; r++)
                v[r] = __ldcs((const float4*)(in + base + (long)r * FS_STRIDE + tok4));
        } else if (lane < 30) {
            #pragma unroll
            for (int r = 0; r < FS; r++)
                vs[r] = __ldcs(in + base + (long)r * FS_STRIDE + toke);
        }
    }

    // ===================== grid-wide barrier (sense-reversing) ===============
    __syncthreads();
    if (tid == 0) {
        __threadfence();                                  // publish phase-1 stores
        unsigned old = atomicAdd(&g_count, 1);
        if (old == B1 - 1) {
            g_count = 0;                                  // reset for next run
            __threadfence();
            g_sense = cur_sense ^ 1u;                     // release all
        } else {
            while (g_sense == cur_sense) __nanosleep(64);
            __threadfence();                              // acquire
        }
    }
    __syncthreads();

    // ===================== global max from partials ==========================
    float pm = __ldcg(&g_partial[tid]);                   // tid < 256 < B1
    if (tid + THR < B1) pm = fmaxf(pm, __ldcg(&g_partial[tid + THR]));
    #pragma unroll
    for (int off = 16; off; off >>= 1)
        pm = fmaxf(pm, __shfl_xor_sync(0xffffffffu, pm, off));
    if (lane == 0) sm[wid] = pm;
    __syncthreads();
    if (tid < 8) {
        pm = sm[tid];
        #pragma unroll
        for (int off = 4; off; off >>= 1)
            pm = fmaxf(pm, __shfl_xor_sync(0xffu, pm, off));
        if (tid == 0) s_gmax = pm;
    }
    __syncthreads();
    const float gmax = s_gmax;

    // ===================== phase 2: strengthen stores ========================
    if (active) {
        const float add = 0.125f * gauss * gmax;
        if (lane < 24) {
            #pragma unroll
            for (int r = 0; r < FS; r++)
                __stcs((float4*)(out + base + (long)r * FS_STRIDE + tok4),
                       make_float4(v[r].x + add, v[r].y + add,
                                   v[r].z + add, v[r].w + add));
        } else if (lane < 30) {
            #pragma unroll
            for (int r = 0; r < FS; r++)
                __stcs(out + base + (long)r * FS_STRIDE + toke, vs[r] + add);
        }
    }

    // remaining positions 3600..3839 (first 240 warps), not preloaded
    const int gw2 = gw + 3600;
    if (gw2 < B_POS) {
        int p2 = gw2;
        const int xo = p2 % 10;  p2 /= 10;
        const int yr = p2 & 15;
        const int f2 = p2 >> 4;
        const int w2 = c_w[f2];
        if (xo < w2) {
            const float add2 = 0.125f * gauss_w(yr, xo, w2) * gmax;
            const long b2 = (long)(f2 * FS * DY + 8 + yr) * DX * SEQL
                          + (long)(c_left[f2] + xo) * SEQL;
            if (lane < 24) {
                #pragma unroll
                for (int r = 0; r < FS; r++) {
                    const long a = b2 + (long)r * FS_STRIDE + tok4;
                    float4 x = __ldcs((const float4*)(in + a));
                    __stcs((float4*)(out + a),
                           make_float4(x.x + add2, x.y + add2,
                                       x.z + add2, x.w + add2));
                }
            } else if (lane < 30) {
                #pragma unroll
                for (int r = 0; r < FS; r++) {
                    const long a = b2 + (long)r * FS_STRIDE + toke;
                    __stcs(out + a, __ldcs(in + a) + add2);
                }
            }
        }
    }
}

extern "C" void kernel_launch(void* const* d_in, const int* in_sizes, int n_in,
                              void* d_out, int out_size) {
    const float* in = (const float*)d_in[0];
    float* out = (float*)d_out;
    fused_kernel<<<B1, THR>>>((const float4*)in, (float4*)out, in, out);
}

// round 10
// speedup vs baseline: 1.0040x; 1.0040x over previous
#include <cuda_runtime.h>
#include <math.h>

#define NF   24
#define FS   8
#define DY   32
#define DX   32
#define SEQL 300
#define TOTAL (NF*FS*DY*DX*SEQL)   // 58,982,400 floats
#define N4    (TOTAL/4)            // 14,745,600 float4
#define ROW4  75

#define B1    450                  // 450 blocks * 256 thr, all co-resident at 4/SM
#define THR   256
#define T1    (B1*THR)             // 115200 = 75*1536 -> t%75 loop-invariant
#define SLOTS (N4/T1)              // 128 float4 per thread

#define FS_STRIDE (DY*DX*SEQL)     // 307200 floats between fs slices
#define B_POS     (NF*16*10)       // 3840 bbox spatial positions

__device__ float    g_partial[B1];
__device__ unsigned g_count;           // returns to 0 after every run (zero-init)
__device__ volatile unsigned g_sense;  // flips each run (sense-reversing barrier)

// Hand-evaluated Python bbox math: left = int(32*l), w = int(32*round(l+0.3,4)) - left
__constant__ int c_left[NF] = {
    1, 2, 2, 3, 4, 5, 5, 6, 7, 7, 8, 9,
    9, 10, 11, 12, 12, 13, 14, 14, 15, 16, 16, 17
};
__constant__ int c_w[NF] = {
    10, 9, 10, 10, 9, 9, 10, 10, 9, 10, 10, 9,
    10, 10, 9, 9, 10, 10, 9, 10, 10, 9, 10, 10
};
__constant__ int c_edge_tok[6] = {2, 3, 9, 10, 11, 108};

__device__ __forceinline__ bool sel_tok(int s) {
    return ((unsigned)(s - 9) < 100u) || ((s & ~1) == 2);
}

// normalized gaussian weight for (yrow, xoff) given bbox width w (9 or 10)
__device__ __forceinline__ float gauss_w(int yrow, int xoff, int w) {
    const float dx = (float)yrow * (16.0f / 15.0f) - 8.0f;
    float ax = ((8.0f / 15.0f) * (8.0f / 15.0f) - dx * dx) * (9.0f / 512.0f);
    float dy, dymin2, inv2sy2;
    if (w == 10) {
        dy = (float)xoff * (10.0f / 9.0f) - 5.0f;
        dymin2 = (5.0f / 9.0f) * (5.0f / 9.0f);
        inv2sy2 = 9.0f / 200.0f;
    } else {
        dy = (float)xoff * (9.0f / 8.0f) - 4.0f;
        dymin2 = 0.25f;
        inv2sy2 = 1.0f / 18.0f;
    }
    return __expf(ax + (dymin2 - dy * dy) * inv2sy2);
}

// one warp handles all 8 fs-rows of one bbox position (loads batched, MLP 8)
__device__ __forceinline__ void strengthen_pos(
    int gw, int lane, float gmax,
    const float* __restrict__ in, float* __restrict__ out)
{
    int pos = gw;
    const int xoff = pos % 10;  pos /= 10;
    const int yrow = pos & 15;
    const int f    = pos >> 4;
    const int w    = c_w[f];
    if (xoff >= w) return;                       // warp-uniform

    const float add = 0.125f * gauss_w(yrow, xoff, w) * gmax;
    const long base = (long)(f * FS * DY + 8 + yrow) * DX * SEQL
                    + (long)(c_left[f] + xoff) * SEQL;

    if (lane < 24) {
        const int tok = 12 + 4 * lane;           // 16B-aligned: row*300 ≡ 0 mod 4
        float4 v[FS];
        #pragma unroll
        for (int r = 0; r < FS; r++)
            v[r] = __ldcs((const float4*)(in + base + (long)r * FS_STRIDE + tok));
        #pragma unroll
        for (int r = 0; r < FS; r++)
            __stcs((float4*)(out + base + (long)r * FS_STRIDE + tok),
                   make_float4(v[r].x + add, v[r].y + add,
                               v[r].z + add, v[r].w + add));
    } else if (lane < 30) {
        const int tok = c_edge_tok[lane - 24];
        float v[FS];
        #pragma unroll
        for (int r = 0; r < FS; r++)
            v[r] = __ldcs(in + base + (long)r * FS_STRIDE + tok);
        #pragma unroll
        for (int r = 0; r < FS; r++)
            __stcs(out + base + (long)r * FS_STRIDE + tok, v[r] + add);
    }
}

__global__ void __launch_bounds__(THR, 4)
fused_kernel(const float4* __restrict__ in4, float4* __restrict__ out4,
             const float* __restrict__ in, float* __restrict__ out) {
    const int tid  = threadIdx.x;
    const int bid  = blockIdx.x;
    const int lane = tid & 31;
    const int wid  = tid >> 5;
    const unsigned cur_sense = g_sense;   // read before anyone can flip it

    __shared__ float sm[8];
    __shared__ float s_gmax;

    // ============ phase 1: weaken + max (472 MB stream, no spills) ===========
    const int t  = bid * THR + tid;
    const int s0 = (t % ROW4) * 4;        // invariant across all 128 slots
    float4 m;
    m.x = sel_tok(s0    ) ? 0.918f : 1.0f;
    m.y = sel_tok(s0 + 1) ? 0.918f : 1.0f;
    m.z = sel_tok(s0 + 2) ? 0.918f : 1.0f;
    m.w = sel_tok(s0 + 3) ? 0.918f : 1.0f;

    float mx = 0.f;
    #pragma unroll 4
    for (int k = 0; k < SLOTS; k++) {
        const int i = t + k * T1;
        float4 x = __ldcs(in4 + i);
        mx = fmaxf(mx, fmaxf(fmaxf(x.x, x.y), fmaxf(x.z, x.w)));
        __stcs(out4 + i, make_float4(x.x * m.x, x.y * m.y, x.z * m.z, x.w * m.w));
    }

    // block max -> g_partial[bid]
    #pragma unroll
    for (int off = 16; off; off >>= 1)
        mx = fmaxf(mx, __shfl_xor_sync(0xffffffffu, mx, off));
    if (lane == 0) sm[wid] = mx;
    __syncthreads();
    if (tid < 8) {
        mx = sm[tid];
        #pragma unroll
        for (int off = 4; off; off >>= 1)
            mx = fmaxf(mx, __shfl_xor_sync(0xffu, mx, off));
        if (tid == 0) g_partial[bid] = mx;
    }

    // ================= grid-wide barrier (sense-reversing) ===================
    __syncthreads();
    if (tid == 0) {
        __threadfence();                                  // publish g_partial
        unsigned old = atomicAdd(&g_count, 1);
        if (old == B1 - 1) {
            g_count = 0;                                  // reset for next replay
            __threadfence();
            g_sense = cur_sense ^ 1u;                     // release
        } else {
            while (g_sense == cur_sense) __nanosleep(64);
            __threadfence();                              // acquire
        }
    }
    __syncthreads();

    // ================= global max from 450 partials ==========================
    float pm = __ldcg(&g_partial[tid]);                   // tid < 256 < B1
    if (tid + THR < B1) pm = fmaxf(pm, __ldcg(&g_partial[tid + THR]));
    #pragma unroll
    for (int off = 16; off; off >>= 1)
        pm = fmaxf(pm, __shfl_xor_sync(0xffffffffu, pm, off));
    if (lane == 0) sm[wid] = pm;
    __syncthreads();
    if (tid < 8) {
        pm = sm[tid];
        #pragma unroll
        for (int off = 4; off; off >>= 1)
            pm = fmaxf(pm, __shfl_xor_sync(0xffu, pm, off));
        if (tid == 0) s_gmax = pm;
    }
    __syncthreads();
    const float gmax = s_gmax;

    // ================= phase 2: strengthen (~25 MB, chip idle) ===============
    const int gw = bid * 8 + wid;                 // 3600 warps
    strengthen_pos(gw, lane, gmax, in, out);      // positions 0..3599
    const int gw2 = gw + 3600;
    if (gw2 < B_POS)
        strengthen_pos(gw2, lane, gmax, in, out); // positions 3600..3839
}

extern "C" void kernel_launch(void* const* d_in, const int* in_sizes, int n_in,
                              void* d_out, int out_size) {
    const float* in = (const float*)d_in[0];
    float* out = (float*)d_out;
    fused_kernel<<<B1, THR>>>((const float4*)in, (float4*)out, in, out);
}

// round 11
// speedup vs baseline: 1.2704x; 1.2653x over previous
#include <cuda_runtime.h>
#include <math.h>

#define NF   24
#define FS   8
#define DY   32
#define DX   32
#define SEQL 300
#define TOTAL (NF*FS*DY*DX*SEQL)   // 58,982,400 floats
#define N4    (TOTAL/4)            // 14,745,600 float4
#define ROW4  75

#define B1    1125                 // <= 1184 (148 SMs * 8 blocks @ <=32 regs): co-resident
#define THR   256
#define T1    (B1*THR)             // 288000 = 75*3840 -> t%75 loop-invariant
#define SLOTS 52                   // ceil(N4/T1), guarded

#define FS_STRIDE (DY*DX*SEQL)     // 307200 floats between fs slices
#define B_POS     (NF*16*10)       // 3840 bbox spatial positions

__device__ float    g_partial[B1];
__device__ unsigned g_count;           // returns to 0 after every run (zero-init)
__device__ volatile unsigned g_sense;  // flips each run (sense-reversing barrier)

// Hand-evaluated Python bbox math: left = int(32*l), w = int(32*round(l+0.3,4)) - left
__constant__ int c_left[NF] = {
    1, 2, 2, 3, 4, 5, 5, 6, 7, 7, 8, 9,
    9, 10, 11, 12, 12, 13, 14, 14, 15, 16, 16, 17
};
__constant__ int c_w[NF] = {
    10, 9, 10, 10, 9, 9, 10, 10, 9, 10, 10, 9,
    10, 10, 9, 9, 10, 10, 9, 10, 10, 9, 10, 10
};
__constant__ int c_edge_tok[6] = {2, 3, 9, 10, 11, 108};

__device__ __forceinline__ bool sel_tok(int s) {
    return ((unsigned)(s - 9) < 100u) || ((s & ~1) == 2);
}

// normalized gaussian weight for (yrow, xoff) given bbox width w (9 or 10)
__device__ __forceinline__ float gauss_w(int yrow, int xoff, int w) {
    const float dx = (float)yrow * (16.0f / 15.0f) - 8.0f;
    float ax = ((8.0f / 15.0f) * (8.0f / 15.0f) - dx * dx) * (9.0f / 512.0f);
    float dy, dymin2, inv2sy2;
    if (w == 10) {
        dy = (float)xoff * (10.0f / 9.0f) - 5.0f;
        dymin2 = (5.0f / 9.0f) * (5.0f / 9.0f);
        inv2sy2 = 9.0f / 200.0f;
    } else {
        dy = (float)xoff * (9.0f / 8.0f) - 4.0f;
        dymin2 = 0.25f;
        inv2sy2 = 1.0f / 18.0f;
    }
    return __expf(ax + (dymin2 - dy * dy) * inv2sy2);
}

__global__ void __launch_bounds__(THR, 8)
fused_kernel(const float4* __restrict__ in4, float4* __restrict__ out4,
             const float* __restrict__ in, float* __restrict__ out) {
    const int tid  = threadIdx.x;
    const int bid  = blockIdx.x;
    const int lane = tid & 31;
    const int wid  = tid >> 5;
    const unsigned cur_sense = g_sense;   // read before anyone flips it

    __shared__ float sm[8];
    __shared__ float s_gmax;

    // ============ phase 1: weaken + max (472 MB stream) ======================
    const int t  = bid * THR + tid;
    const int s0 = (t % ROW4) * 4;        // invariant: stride 288000 = 75*3840
    float4 m;
    m.x = sel_tok(s0    ) ? 0.918f : 1.0f;
    m.y = sel_tok(s0 + 1) ? 0.918f : 1.0f;
    m.z = sel_tok(s0 + 2) ? 0.918f : 1.0f;
    m.w = sel_tok(s0 + 3) ? 0.918f : 1.0f;

    float mx = 0.f;
    #pragma unroll 4
    for (int k = 0; k < SLOTS; k++) {
        const int i = t + k * T1;
        if (i < N4) {
            float4 x = __ldcs(in4 + i);
            mx = fmaxf(mx, fmaxf(fmaxf(x.x, x.y), fmaxf(x.z, x.w)));
            __stcs(out4 + i,
                   make_float4(x.x * m.x, x.y * m.y, x.z * m.z, x.w * m.w));
        }
    }

    // block max -> g_partial[bid]
    #pragma unroll
    for (int off = 16; off; off >>= 1)
        mx = fmaxf(mx, __shfl_xor_sync(0xffffffffu, mx, off));
    if (lane == 0) sm[wid] = mx;
    __syncthreads();
    if (tid < 8) {
        mx = sm[tid];
        #pragma unroll
        for (int off = 4; off; off >>= 1)
            mx = fmaxf(mx, __shfl_xor_sync(0xffu, mx, off));
        if (tid == 0) g_partial[bid] = mx;
    }

    // ================= grid-wide barrier (sense-reversing) ===================
    __syncthreads();
    if (tid == 0) {
        __threadfence();                                  // publish g_partial
        unsigned old = atomicAdd(&g_count, 1);
        if (old == B1 - 1) {
            g_count = 0;                                  // reset for next replay
            __threadfence();
            g_sense = cur_sense ^ 1u;                     // release
        } else {
            while (g_sense == cur_sense) __nanosleep(64);
            __threadfence();                              // acquire
        }
    }
    __syncthreads();

    // ================= global max from 1125 partials =========================
    float pm = 0.f;
    #pragma unroll
    for (int j = tid; j < B1; j += THR)                   // 5 strided reads
        pm = fmaxf(pm, __ldcg(&g_partial[j]));
    #pragma unroll
    for (int off = 16; off; off >>= 1)
        pm = fmaxf(pm, __shfl_xor_sync(0xffffffffu, pm, off));
    if (lane == 0) sm[wid] = pm;
    __syncthreads();
    if (tid < 8) {
        pm = sm[tid];
        #pragma unroll
        for (int off = 4; off; off >>= 1)
            pm = fmaxf(pm, __shfl_xor_sync(0xffu, pm, off));
        if (tid == 0) s_gmax = pm;
    }
    __syncthreads();
    const float gmax = s_gmax;

    // ======== phase 2: strengthen. warp per (position, fs-half), 7680 warps ==
    const int W = bid * 8 + wid;          // [0, 9000)
    if (W >= B_POS * 2) return;
    const int half = W & 1;
    int pos = W >> 1;
    const int xoff = pos % 10;  pos /= 10;
    const int yrow = pos & 15;
    const int f    = pos >> 4;
    const int w    = c_w[f];
    if (xoff >= w) return;                // warp-uniform

    const float add = 0.125f * gauss_w(yrow, xoff, w) * gmax;
    const long base = (long)((f * FS + half * 4) * DY + 8 + yrow) * DX * SEQL
                    + (long)(c_left[f] + xoff) * SEQL;

    if (lane < 24) {
        const int tok = 12 + 4 * lane;    // 16B-aligned: row*300 ≡ 0 mod 4
        float4 v[4];
        #pragma unroll
        for (int r = 0; r < 4; r++)
            v[r] = __ldcs((const float4*)(in + base + (long)r * FS_STRIDE + tok));
        #pragma unroll
        for (int r = 0; r < 4; r++)
            __stcs((float4*)(out + base + (long)r * FS_STRIDE + tok),
                   make_float4(v[r].x + add, v[r].y + add,
                               v[r].z + add, v[r].w + add));
    } else if (lane < 30) {
        const int tok = c_edge_tok[lane - 24];
        float v[4];
        #pragma unroll
        for (int r = 0; r < 4; r++)
            v[r] = __ldcs(in + base + (long)r * FS_STRIDE + tok);
        #pragma unroll
        for (int r = 0; r < 4; r++)
            __stcs(out + base + (long)r * FS_STRIDE + tok, v[r] + add);
    }
}

extern "C" void kernel_launch(void* const* d_in, const int* in_sizes, int n_in,
                              void* d_out, int out_size) {
    const float* in = (const float*)d_in[0];
    float* out = (float*)d_out;
    fused_kernel<<<B1, THR>>>((const float4*)in, (float4*)out, in, out);
}